// round 16
// baseline (speedup 1.0000x reference)
#include <cuda_runtime.h>
#include <cuda_bf16.h>
#include <stdint.h>

// Problem constants
#define S_TOTAL   4096
#define W_WIDTH   16
#define N_NODES   193
#define NDIM      2
#define P_ORDER   4
#define ROW_F     (N_NODES * NDIM)                        // 386 floats per (s,w) row
#define BLK_F     (W_WIDTH * ROW_F)                       // 6176 floats per (array,sample)
#define BLK_F4    (BLK_F / 4)                             // 1544 float4
#define SCAT_ELEMS (S_TOTAL * W_WIDTH * N_NODES * NDIM)   // 25,296,896

// Output layout (float offsets), reference return order
#define OFF_T     0
#define OFF_DT    (S_TOTAL * W_WIDTH)                     // 65536
#define OFF_DDT   (2 * S_TOTAL * W_WIDTH)                 // 131072
#define OFF_PHI   (3 * S_TOTAL * W_WIDTH)                 // 196608 (float4-aligned)
#define OFF_DX    (OFF_PHI + 3 * SCAT_ELEMS)              // 76,087,296

#define DELTA_X 0.0078125f                                // 1/128 exactly
#define INV_DX  128.0f
#define INV_DX2 16384.0f

__global__ __launch_bounds__(256)
void lagr_kann_kernel(const float* __restrict__ x,
                      const float* __restrict__ weight,
                      float* __restrict__ out)
{
    const int s   = blockIdx.x;
    const int tid = threadIdx.x;

    __shared__ int   scol[8];        // scatter column per (d,j):  e = d*4 + j
    __shared__ float sval[3][8];     // phi / dphi / ddphi values

    // ---- 8 threads compute the Lagrange basis (e = tid: d = tid>>2, j = tid&3) ----
    if (tid < 8) {
        const int dd = tid >> 2;
        const int jj = tid & 3;
        const float xv = x[s * 2 + dd];
        const float xs = 192.0f * xv;                      // x_shift
        float fel = floorf(xs / 3.0f);
        fel = fminf(fmaxf(fel, 0.0f), 63.0f);
        const int nl = (int)(fel * 3.0f);                  // left node index
        const float xr = 2.0f * (xs - (float)nl) / 3.0f - 1.0f;

        const float nodes[4] = { -1.0f, -1.0f / 3.0f, 1.0f / 3.0f, 1.0f };

        // value
        float pv;
        {
            float p = 1.0f;
            #pragma unroll
            for (int m = 0; m < P_ORDER; m++)
                if (m != jj) p *= (xr - nodes[m]) / (nodes[jj] - nodes[m]);
            pv = p;
        }
        // first derivative
        float dv;
        {
            float y1 = 0.0f;
            #pragma unroll
            for (int i2 = 0; i2 < P_ORDER; i2++) {
                if (i2 == jj) continue;
                float k = 1.0f / (nodes[jj] - nodes[i2]);
                #pragma unroll
                for (int m = 0; m < P_ORDER; m++)
                    if (m != i2 && m != jj) k *= (xr - nodes[m]) / (nodes[jj] - nodes[m]);
                y1 += k;
            }
            dv = y1 * INV_DX;
        }
        // second derivative
        float ddv;
        {
            float y2 = 0.0f;
            #pragma unroll
            for (int i2 = 0; i2 < P_ORDER; i2++) {
                if (i2 == jj) continue;
                float ks = 0.0f;
                #pragma unroll
                for (int m = 0; m < P_ORDER; m++) {
                    if (m == i2 || m == jj) continue;
                    float kp = 1.0f / (nodes[jj] - nodes[m]);
                    #pragma unroll
                    for (int n = 0; n < P_ORDER; n++)
                        if (n != i2 && n != jj && n != m)
                            kp *= (xr - nodes[n]) / (nodes[jj] - nodes[n]);
                    ks += kp;
                }
                y2 += ks / (nodes[jj] - nodes[i2]);
            }
            ddv = y2 * INV_DX2;
        }

        scol[tid]    = (nl + jj) * 2 + dd;
        sval[0][tid] = pv;
        sval[1][tid] = dv;
        sval[2][tid] = ddv;
    }

    // ---- bulk zero-fill: 3 contiguous 6176-float blocks, float4 stores ----
    const float4 z = make_float4(0.0f, 0.0f, 0.0f, 0.0f);
    {
        float4* p0 = (float4*)(out + OFF_PHI) + (size_t)s * BLK_F4;
        float4* p1 = p0 + (size_t)(SCAT_ELEMS / 4);
        float4* p2 = p1 + (size_t)(SCAT_ELEMS / 4);
        #pragma unroll
        for (int i = tid; i < BLK_F4; i += 256) p0[i] = z;
        #pragma unroll
        for (int i = tid; i < BLK_F4; i += 256) p1[i] = z;
        #pragma unroll
        for (int i = tid; i < BLK_F4; i += 256) p2[i] = z;
    }

    __syncthreads();   // orders zero-fill before nonzero overwrites; sval/scol visible

    // ---- scatter the 384 nonzeros (3 arrays x 16 widths x 8 basis entries) ----
    {
        float* base = out + OFF_PHI + (size_t)s * BLK_F;
        for (int idx = tid; idx < 384; idx += 256) {
            const int a = idx >> 7;          // array 0..2
            const int r = idx & 127;
            const int w = r >> 3;            // width 0..15
            const int e = r & 7;             // basis entry 0..7
            base[(size_t)a * SCAT_ELEMS + w * ROW_F + scol[e]] = sval[a][e];
        }
    }

    // ---- einsum reductions: 16 threads, one per width k ----
    if (tid < 16) {
        const int k = tid;
        const float* wk = weight + k * ROW_F;
        float t = 0.0f, dt = 0.0f, ddt = 0.0f;
        #pragma unroll
        for (int e = 0; e < 8; e++) {
            const float wv = wk[scol[e]];
            t   += wv * sval[0][e];
            dt  += wv * sval[1][e];
            ddt += wv * sval[2][e];
        }
        out[OFF_T   + s * W_WIDTH + k] = t;
        out[OFF_DT  + s * W_WIDTH + k] = dt;
        out[OFF_DDT + s * W_WIDTH + k] = ddt;
    }

    // ---- delta_x scalar ----
    if (s == 0 && tid == 0) out[OFF_DX] = DELTA_X;
}

extern "C" void kernel_launch(void* const* d_in, const int* in_sizes, int n_in,
                              void* d_out, int out_size)
{
    const float* x      = (const float*)d_in[0];   // (4096, 2)
    const float* weight = (const float*)d_in[1];   // (16, 193, 2)
    float* out = (float*)d_out;
    lagr_kann_kernel<<<S_TOTAL, 256>>>(x, weight, out);
}

// round 17
// speedup vs baseline: 1.0251x; 1.0251x over previous
#include <cuda_runtime.h>
#include <cuda_bf16.h>
#include <stdint.h>

// Problem constants
#define S_TOTAL   4096
#define W_WIDTH   16
#define N_NODES   193
#define NDIM      2
#define P_ORDER   4
#define ROW_F     (N_NODES * NDIM)                        // 386 floats per (s,w) row
#define BLK_F     (W_WIDTH * ROW_F)                       // 6176 floats per (array,sample)
#define BLK_F4    (BLK_F / 4)                             // 1544 float4
#define SCAT_ELEMS (S_TOTAL * W_WIDTH * N_NODES * NDIM)   // 25,296,896

// Output layout (float offsets), reference return order
#define OFF_T     0
#define OFF_DT    (S_TOTAL * W_WIDTH)                     // 65536
#define OFF_DDT   (2 * S_TOTAL * W_WIDTH)                 // 131072
#define OFF_PHI   (3 * S_TOTAL * W_WIDTH)                 // 196608 (float4-aligned)
#define OFF_DX    (OFF_PHI + 3 * SCAT_ELEMS)              // 76,087,296

#define DELTA_X 0.0078125f                                // 1/128 exactly
#define INV_DX  128.0f
#define INV_DX2 16384.0f

__global__ __launch_bounds__(256)
void lagr_kann_kernel(const float* __restrict__ x,
                      const float* __restrict__ weight,
                      float* __restrict__ out)
{
    const int s   = blockIdx.x;
    const int tid = threadIdx.x;

    __shared__ int   scol[8];        // scatter column per (d,j):  e = d*4 + j
    __shared__ float sval[3][8];     // phi / dphi / ddphi values

    // ---- 8 threads compute the Lagrange basis (e = tid: d = tid>>2, j = tid&3) ----
    if (tid < 8) {
        const int dd = tid >> 2;
        const int jj = tid & 3;
        const float xv = x[s * 2 + dd];
        const float xs = 192.0f * xv;                      // x_shift
        float fel = floorf(xs / 3.0f);
        fel = fminf(fmaxf(fel, 0.0f), 63.0f);
        const int nl = (int)(fel * 3.0f);                  // left node index
        const float xr = 2.0f * (xs - (float)nl) / 3.0f - 1.0f;

        const float nodes[4] = { -1.0f, -1.0f / 3.0f, 1.0f / 3.0f, 1.0f };

        // value
        float pv;
        {
            float p = 1.0f;
            #pragma unroll
            for (int m = 0; m < P_ORDER; m++)
                if (m != jj) p *= (xr - nodes[m]) / (nodes[jj] - nodes[m]);
            pv = p;
        }
        // first derivative
        float dv;
        {
            float y1 = 0.0f;
            #pragma unroll
            for (int i2 = 0; i2 < P_ORDER; i2++) {
                if (i2 == jj) continue;
                float k = 1.0f / (nodes[jj] - nodes[i2]);
                #pragma unroll
                for (int m = 0; m < P_ORDER; m++)
                    if (m != i2 && m != jj) k *= (xr - nodes[m]) / (nodes[jj] - nodes[m]);
                y1 += k;
            }
            dv = y1 * INV_DX;
        }
        // second derivative
        float ddv;
        {
            float y2 = 0.0f;
            #pragma unroll
            for (int i2 = 0; i2 < P_ORDER; i2++) {
                if (i2 == jj) continue;
                float ks = 0.0f;
                #pragma unroll
                for (int m = 0; m < P_ORDER; m++) {
                    if (m == i2 || m == jj) continue;
                    float kp = 1.0f / (nodes[jj] - nodes[m]);
                    #pragma unroll
                    for (int n = 0; n < P_ORDER; n++)
                        if (n != i2 && n != jj && n != m)
                            kp *= (xr - nodes[n]) / (nodes[jj] - nodes[n]);
                    ks += kp;
                }
                y2 += ks / (nodes[jj] - nodes[i2]);
            }
            ddv = y2 * INV_DX2;
        }

        scol[tid]    = (nl + jj) * 2 + dd;
        sval[0][tid] = pv;
        sval[1][tid] = dv;
        sval[2][tid] = ddv;
    }

    // ---- bulk zero-fill: 3 contiguous 6176-float blocks, float4 stores ----
    const float4 z = make_float4(0.0f, 0.0f, 0.0f, 0.0f);
    {
        float4* p0 = (float4*)(out + OFF_PHI) + (size_t)s * BLK_F4;
        float4* p1 = p0 + (size_t)(SCAT_ELEMS / 4);
        float4* p2 = p1 + (size_t)(SCAT_ELEMS / 4);
        #pragma unroll
        for (int i = tid; i < BLK_F4; i += 256) p0[i] = z;
        #pragma unroll
        for (int i = tid; i < BLK_F4; i += 256) p1[i] = z;
        #pragma unroll
        for (int i = tid; i < BLK_F4; i += 256) p2[i] = z;
    }

    __syncthreads();   // orders zero-fill before nonzero overwrites; sval/scol visible

    // ---- scatter the 384 nonzeros (3 arrays x 16 widths x 8 basis entries) ----
    {
        float* base = out + OFF_PHI + (size_t)s * BLK_F;
        for (int idx = tid; idx < 384; idx += 256) {
            const int a = idx >> 7;          // array 0..2
            const int r = idx & 127;
            const int w = r >> 3;            // width 0..15
            const int e = r & 7;             // basis entry 0..7
            base[(size_t)a * SCAT_ELEMS + w * ROW_F + scol[e]] = sval[a][e];
        }
    }

    // ---- einsum reductions: 16 threads, one per width k ----
    if (tid < 16) {
        const int k = tid;
        const float* wk = weight + k * ROW_F;
        float t = 0.0f, dt = 0.0f, ddt = 0.0f;
        #pragma unroll
        for (int e = 0; e < 8; e++) {
            const float wv = wk[scol[e]];
            t   += wv * sval[0][e];
            dt  += wv * sval[1][e];
            ddt += wv * sval[2][e];
        }
        out[OFF_T   + s * W_WIDTH + k] = t;
        out[OFF_DT  + s * W_WIDTH + k] = dt;
        out[OFF_DDT + s * W_WIDTH + k] = ddt;
    }

    // ---- delta_x scalar ----
    if (s == 0 && tid == 0) out[OFF_DX] = DELTA_X;
}

extern "C" void kernel_launch(void* const* d_in, const int* in_sizes, int n_in,
                              void* d_out, int out_size)
{
    const float* x      = (const float*)d_in[0];   // (4096, 2)
    const float* weight = (const float*)d_in[1];   // (16, 193, 2)
    float* out = (float*)d_out;
    lagr_kann_kernel<<<S_TOTAL, 256>>>(x, weight, out);
}